// round 11
// baseline (speedup 1.0000x reference)
#include <cuda_runtime.h>
#include <cuda_fp16.h>
#include <math.h>
#include <stdint.h>

#define NROWS 32768      // B*S
#define FFN   2048
#define EMB   512

// ---------------- scratch ---------------------------------------------------
__device__ __half g_EVh[NROWS * 8];     // 512 KB (fp16 EV)
__device__ __half g_Wh [EMB * FFN];     // 2 MB   (fp16 W2)
__device__ __half g_W1h[FFN * 8];       // 32 KB  (fp16 W1)

// ---------------------------------------------------------------------------
// Kernel 1: quantum circuit collapsed to closed form (verified R1/R2),
// now emitting fp16 EV directly.
// ---------------------------------------------------------------------------
__global__ void ev_kernel(const float* __restrict__ x,
                          const float* __restrict__ params) {
    int row = blockIdx.x * blockDim.x + threadIdx.x;
    if (row >= NROWS) return;
    float z[8];
#pragma unroll
    for (int i = 0; i < 8; i++) {
        float a = params[i * 3 + 0];
        float b = params[i * 3 + 1];
        float c = params[i * 3 + 2];
        float sa, ca, sb, cb, sc, cc;
        sincosf(a, &sa, &ca);
        sincosf(b, &sb, &cb);
        sincosf(c, &sc, &cc);
        float Acoef = ca * cc + sa * sb * sc;
        float Ccoef = cb * sc;
        float sx, cx;
        sincosf(x[row * 8 + i], &sx, &cx);
        z[i] = Acoef * cx - Ccoef * sx;
    }
    float ev[8];
    float pre = z[0];
#pragma unroll
    for (int k = 1; k < 8; k++) { pre *= z[k]; ev[k] = pre; }
    float suf = 1.0f;
#pragma unroll
    for (int k = 7; k >= 1; k--) suf *= z[k];
    ev[0] = suf;
    __align__(16) __half evh[8];
#pragma unroll
    for (int k = 0; k < 8; k++) evh[k] = __float2half(ev[k]);
    *(uint4*)&g_EVh[row * 8] = *(const uint4*)evh;
}

// ---------------------------------------------------------------------------
// Kernel 2: W2 -> fp16
// ---------------------------------------------------------------------------
__global__ void w_half_kernel(const float* __restrict__ W2) {
    int idx = blockIdx.x * blockDim.x + threadIdx.x;   // [0, EMB*FFN/2)
    float2 v = ((const float2*)W2)[idx];
    ((__half2*)g_Wh)[idx] = __floats2half2_rn(v.x, v.y);
}

// ---------------------------------------------------------------------------
// Kernel 3: W1 -> fp16 (one row of 8 per thread)
// ---------------------------------------------------------------------------
__global__ void w1_half_kernel(const float* __restrict__ W1) {
    int r = blockIdx.x * blockDim.x + threadIdx.x;     // [0, FFN)
    float4 v0 = *(const float4*)&W1[r * 8];
    float4 v1 = *(const float4*)&W1[r * 8 + 4];
    __align__(16) __half h[8];
    h[0] = __float2half(v0.x); h[1] = __float2half(v0.y);
    h[2] = __float2half(v0.z); h[3] = __float2half(v0.w);
    h[4] = __float2half(v1.x); h[5] = __float2half(v1.y);
    h[6] = __float2half(v1.z); h[7] = __float2half(v1.w);
    *(uint4*)&g_W1h[r * 8] = *(const uint4*)h;
}

// ---------------------------------------------------------------------------
// Kernel 4 (fused): OUT = relu(EV@W1^T + b1) @ W2^T + b2.
// A fragments produced ON TENSOR CORE: m16n8k8 H-mma (EV x W1, bias-in-C),
// relu+pack fp32->half2 lands directly in m16n8k16 A-operand layout.
// CTA 128x64, BK=64, 4 warps (2x2), B-only 3-stage cp.async (8KB/stage),
// 24KB static smem, 3 CTAs/SM.
// ---------------------------------------------------------------------------
#define BM 128
#define BN 64
#define BK 64
#define NT (FFN / BK)             // 32
#define STG 8192                  // B tile only: 64 rows x 128B

#define CP16(dst, src) \
    asm volatile("cp.async.cg.shared.global [%0], [%1], 16;\n" :: "r"(dst), "l"(src))

__device__ __forceinline__ void ldsm4(unsigned* r, unsigned a) {
    asm volatile("ldmatrix.sync.aligned.m8n8.x4.shared.b16 {%0,%1,%2,%3}, [%4];"
                 : "=r"(r[0]), "=r"(r[1]), "=r"(r[2]), "=r"(r[3]) : "r"(a));
}

__device__ __forceinline__ void mma16816(float* c, const unsigned* a, const unsigned* b) {
    asm volatile("mma.sync.aligned.m16n8k16.row.col.f32.f16.f16.f32 "
                 "{%0,%1,%2,%3}, {%4,%5,%6,%7}, {%8,%9}, {%0,%1,%2,%3};"
                 : "+f"(c[0]), "+f"(c[1]), "+f"(c[2]), "+f"(c[3])
                 : "r"(a[0]), "r"(a[1]), "r"(a[2]), "r"(a[3]), "r"(b[0]), "r"(b[1]));
}

__device__ __forceinline__ void mma16808(float* c, const unsigned* a, unsigned b) {
    asm volatile("mma.sync.aligned.m16n8k8.row.col.f32.f16.f16.f32 "
                 "{%0,%1,%2,%3}, {%4,%5}, {%6}, {%0,%1,%2,%3};"
                 : "+f"(c[0]), "+f"(c[1]), "+f"(c[2]), "+f"(c[3])
                 : "r"(a[0]), "r"(a[1]), "r"(b));
}

// relu + pack two fp32 into an A-operand half2 register
__device__ __forceinline__ unsigned rpack(float x, float y) {
    __half2 h = __floats2half2_rn(x, y);
    h = __hmax2(h, __floats2half2_rn(0.0f, 0.0f));
    return reinterpret_cast<unsigned&>(h);
}

// 128B rows, 8 chunks of 16B, full SW128 swizzle
__device__ __forceinline__ unsigned swz(int row, int ch) {
    return (unsigned)(row * 128 + ((ch ^ (row & 7)) << 4));
}

__device__ __forceinline__ void load_stage(unsigned st, int bn, int tid, int k0) {
#pragma unroll
    for (int i = 0; i < 4; i++) {               // B: 512 chunks of 16B
        int id = tid + (i << 7);
        int r = id >> 3, c = id & 7;
        size_t g = (size_t)(bn + r) * FFN + k0 + c * 8;
        CP16(st + swz(r, c), g_Wh + g);
    }
}

__global__ void __launch_bounds__(128, 3)
mma_gemm(const float* __restrict__ b1, const float* __restrict__ bias,
         float* __restrict__ C) {
    __shared__ __align__(128) unsigned char smem[3 * STG];
    const int tid  = threadIdx.x;
    const int warp = tid >> 5, lane = tid & 31;
    const int wm = warp & 1;                 // 2 m-groups of 64 rows
    const int wn = warp >> 1;                // 2 n-groups of 32 cols
    const int bm = blockIdx.y * BM, bn = blockIdx.x * BN;
    const unsigned sbase = (unsigned)__cvta_generic_to_shared(smem);

    // EV A-fragments (m16k8), one per mf, loaded once (k-invariant)
    unsigned evf[4][2];
#pragma unroll
    for (int mf = 0; mf < 4; mf++) {
        int r = bm + wm * 64 + mf * 16 + (lane >> 2);
        evf[mf][0] = *(const unsigned*)&g_EVh[r * 8 + 2 * (lane & 3)];
        evf[mf][1] = *(const unsigned*)&g_EVh[(r + 8) * 8 + 2 * (lane & 3)];
    }

    float acc[4][4][4];                      // [mf][nf][frag]
#pragma unroll
    for (int i = 0; i < 4; i++)
#pragma unroll
        for (int j = 0; j < 4; j++)
#pragma unroll
            for (int k = 0; k < 4; k++) acc[i][j][k] = 0.0f;

    load_stage(sbase,       bn, tid, 0);
    asm volatile("cp.async.commit_group;\n");
    load_stage(sbase + STG, bn, tid, BK);
    asm volatile("cp.async.commit_group;\n");

    for (int t = 0; t < NT; t++) {
        if (t + 1 < NT) asm volatile("cp.async.wait_group 1;\n" ::: "memory");
        else            asm volatile("cp.async.wait_group 0;\n" ::: "memory");
        __syncthreads();

        if (t + 2 < NT) {
            load_stage(sbase + ((t + 2) % 3) * STG, bn, tid, (t + 2) * BK);
            asm volatile("cp.async.commit_group;\n");
        }

        unsigned st = sbase + (t % 3) * STG;
#pragma unroll
        for (int kk = 0; kk < 4; kk++) {     // four k16 chunks of BK=64
            int ko = t * BK + kk * 16;
            // W1^T B-fragments for the two n8 halves of this k16 chunk
            unsigned w1a = *(const unsigned*)&g_W1h[(ko +     (lane >> 2)) * 8 + 2 * (lane & 3)];
            unsigned w1b = *(const unsigned*)&g_W1h[(ko + 8 + (lane >> 2)) * 8 + 2 * (lane & 3)];
            float2 bva = *(const float2*)&b1[ko +     2 * (lane & 3)];
            float2 bvb = *(const float2*)&b1[ko + 8 + 2 * (lane & 3)];

            unsigned bfr[2][4];
#pragma unroll
            for (int nb = 0; nb < 2; nb++) {     // main-GEMM B frags: n32
                int n  = wn * 32 + nb * 16 + (lane & 7) + ((lane >> 4) & 1) * 8;
                int ch = kk * 2 + ((lane >> 3) & 1);
                ldsm4(bfr[nb], st + swz(n, ch));
            }

#pragma unroll
            for (int mf = 0; mf < 4; mf++) {
                // H-mma: D = EV(m16k8) x W1^T(k8n8) + bias  -> fp32
                float h0[4] = {bva.x, bva.y, bva.x, bva.y};
                float h1[4] = {bvb.x, bvb.y, bvb.x, bvb.y};
                mma16808(h0, evf[mf], w1a);
                mma16808(h1, evf[mf], w1b);
                // relu + pack straight into A-operand layout (m16k16)
                unsigned a[4];
                a[0] = rpack(h0[0], h0[1]);
                a[1] = rpack(h0[2], h0[3]);
                a[2] = rpack(h1[0], h1[1]);
                a[3] = rpack(h1[2], h1[3]);
#pragma unroll
                for (int nf = 0; nf < 4; nf++)
                    mma16816(acc[mf][nf], a, &bfr[nf >> 1][(nf & 1) * 2]);
            }
        }
    }

    // epilogue: add bias b2
#pragma unroll
    for (int mf = 0; mf < 4; mf++) {
        int r0 = bm + wm * 64 + mf * 16 + (lane >> 2);
#pragma unroll
        for (int nf = 0; nf < 4; nf++) {
            int cc = bn + wn * 32 + nf * 8 + (lane & 3) * 2;
            float2 b2 = *(const float2*)&bias[cc];
            float2 v0 = make_float2(acc[mf][nf][0] + b2.x, acc[mf][nf][1] + b2.y);
            float2 v1 = make_float2(acc[mf][nf][2] + b2.x, acc[mf][nf][3] + b2.y);
            *(float2*)&C[(size_t)r0 * EMB + cc]       = v0;
            *(float2*)&C[(size_t)(r0 + 8) * EMB + cc] = v1;
        }
    }
}

// ---------------------------------------------------------------------------
extern "C" void kernel_launch(void* const* d_in, const int* in_sizes, int n_in,
                              void* d_out, int out_size) {
    const float* x      = (const float*)d_in[0];  // [16,2048,8]
    const float* params = (const float*)d_in[1];  // [8,3]
    const float* W1     = (const float*)d_in[2];  // [2048,8]
    const float* b1     = (const float*)d_in[3];  // [2048]
    const float* W2     = (const float*)d_in[4];  // [512,2048]
    const float* b2     = (const float*)d_in[5];  // [512]
    float* out = (float*)d_out;                   // [16,2048,512]

    w_half_kernel<<<(EMB * (FFN / 2)) / 256, 256>>>(W2);
    w1_half_kernel<<<FFN / 256, 256>>>(W1);
    ev_kernel<<<NROWS / 256, 256>>>(x, params);
    mma_gemm<<<dim3(EMB / BN, NROWS / BM), 128>>>(b1, b2, out);
}